// round 16
// baseline (speedup 1.0000x reference)
#include <cuda_runtime.h>
#include <cuda_fp16.h>
#include <mma.h>
#include <math.h>

using namespace nvcuda;

#define N_NODES  50000
#define N_EDGES  800000
#define N_GRAPHS 256
#define FEAT     128
#define STATE    64
#define ROUNDS   4
#define M_OUT    32

#define TILE_ROWS 64
#define HPITCH    72          // half pitch (multiple of 8, conflict-skewed)
#define CPITCH    68          // float pitch for fp32 result tile
#define ROW_BLOCKS ((N_NODES + TILE_ROWS - 1) / TILE_ROWS)   // 782

// Scratch (allocation-free rule: __device__ globals)
__device__ float  g_state[N_NODES * STATE];   // 12.8 MB
__device__ __half g_msg[N_NODES * STATE];     // 6.4 MB (fp16 message buffer)
__device__ float  g_agg[N_NODES * STATE];     // 12.8 MB
__device__ float  g_graph[N_GRAPHS * STATE];  // 64 KB (zeroed by k_scan each call)
// CSR-by-dst scratch (built once per launch, reused all 4 rounds)
__device__ int    g_cnt[N_NODES];             // self-cleaning: k_scan re-zeroes
__device__ int    g_rowptr[N_NODES + 1];
__device__ int    g_cursor[N_NODES];
__device__ int    g_esrc[N_EDGES];

// Side stream + events for CSR||input overlap. Created at static init (no
// device-memory allocation; harness mem checkpoints see no delta).
struct SideStream {
    cudaStream_t s = nullptr;
    cudaEvent_t fork = nullptr, join = nullptr;
    SideStream() {
        cudaStreamCreateWithFlags(&s, cudaStreamNonBlocking);
        cudaEventCreateWithFlags(&fork, cudaEventDisableTiming);
        cudaEventCreateWithFlags(&join, cudaEventDisableTiming);
    }
};
static SideStream g_ss;

// ---------------------------------------------------------------------------
// CSR build: histogram of dst, scan (self-cleaning), scatter of src ids
// g_cnt is zero at entry of every call: zero-initialized at module load, and
// k_scan re-zeroes each element right after consuming it.
// ---------------------------------------------------------------------------
__global__ void k_hist(const int* __restrict__ ei) {
    int t = blockIdx.x * blockDim.x + threadIdx.x;
    if (t < N_EDGES) atomicAdd(&g_cnt[__ldg(&ei[N_EDGES + t])], 1);
}

__global__ __launch_bounds__(1024) void k_scan() {
    __shared__ int ps[1024];
    const int CH = (N_NODES + 1023) / 1024;   // 49
    int t = threadIdx.x;
    int base = t * CH;

    // also zero g_graph for this call's pooling (16384 floats)
    for (int i = t; i < N_GRAPHS * STATE; i += 1024) g_graph[i] = 0.0f;

    int sum = 0;
    for (int i = 0; i < CH; i++) {
        int idx = base + i;
        if (idx < N_NODES) sum += g_cnt[idx];
    }
    ps[t] = sum;
    __syncthreads();
    for (int off = 1; off < 1024; off <<= 1) {
        int v = (t >= off) ? ps[t - off] : 0;
        __syncthreads();
        ps[t] += v;
        __syncthreads();
    }
    int run = (t == 0) ? 0 : ps[t - 1];
    for (int i = 0; i < CH; i++) {
        int idx = base + i;
        if (idx < N_NODES) {
            int c = g_cnt[idx];
            g_cnt[idx] = 0;            // self-clean for next launch/replay
            g_rowptr[idx] = run;
            g_cursor[idx] = run;
            run += c;
        }
    }
    if (t == 1023) g_rowptr[N_NODES] = run;   // = N_EDGES
}

__global__ void k_scatter(const int* __restrict__ ei) {
    int t = blockIdx.x * blockDim.x + threadIdx.x;
    if (t >= N_EDGES) return;
    int d = __ldg(&ei[N_EDGES + t]);
    int pos = atomicAdd(&g_cursor[d], 1);
    g_esrc[pos] = __ldg(&ei[t]);
}

// ===========================================================================
// fp16 helpers
// ===========================================================================
__device__ __forceinline__ float4 ld_msg4(const __half* p) {   // 4 halves (8B)
    uint2 u = *reinterpret_cast<const uint2*>(p);
    float2 f0 = __half22float2(*reinterpret_cast<__half2*>(&u.x));
    float2 f1 = __half22float2(*reinterpret_cast<__half2*>(&u.y));
    return make_float4(f0.x, f0.y, f1.x, f1.y);
}

__device__ __forceinline__ void st_half4(__half* p, float a, float b, float c, float d) {
    uint2 u;
    *reinterpret_cast<__half2*>(&u.x) = __floats2half2_rn(a, b);
    *reinterpret_cast<__half2*>(&u.y) = __floats2half2_rn(c, d);
    *reinterpret_cast<uint2*>(p) = u;
}

// ===========================================================================
// wmma GEMM building blocks (64x64 tile, fp16 in, fp32 acc)
// ===========================================================================
__device__ __forceinline__ void load_tileA_h(__half* sAh, const float* __restrict__ src,
                                             int blkRow, int rowStride, int colOff, int tid) {
#pragma unroll
    for (int p = 0; p < 4; p++) {
        int idx = p * 1024 + tid * 4;
        int row = idx >> 6, col = idx & 63;
        float4 v = make_float4(0.f, 0.f, 0.f, 0.f);
        int gr = blkRow + row;
        if (gr < N_NODES)
            v = *reinterpret_cast<const float4*>(&src[gr * rowStride + colOff + col]);
        st_half4(&sAh[row * HPITCH + col], v.x, v.y, v.z, v.w);
    }
}

__device__ __forceinline__ void load_tileW_h(__half* sBh, const float* __restrict__ W, int tid) {
#pragma unroll
    for (int p = 0; p < 4; p++) {
        int idx = p * 1024 + tid * 4;
        int row = idx >> 6, col = idx & 63;
        float4 v = *reinterpret_cast<const float4*>(&W[idx]);
        st_half4(&sBh[row * HPITCH + col], v.x, v.y, v.z, v.w);
    }
}

template <int ACCUM>
__device__ __forceinline__ void wmma_64x64(float* sC, const __half* sAh, const __half* sBh,
                                           int warp) {
#pragma unroll
    for (int t = 0; t < 2; t++) {
        int tile = warp * 2 + t;
        int tr = tile >> 2, tc = tile & 3;
        wmma::fragment<wmma::accumulator, 16, 16, 16, float> c;
        if (ACCUM)
            wmma::load_matrix_sync(c, sC + tr * 16 * CPITCH + tc * 16, CPITCH,
                                   wmma::mem_row_major);
        else
            wmma::fill_fragment(c, 0.0f);
#pragma unroll
        for (int kk = 0; kk < 4; kk++) {
            wmma::fragment<wmma::matrix_a, 16, 16, 16, __half, wmma::row_major> a;
            wmma::fragment<wmma::matrix_b, 16, 16, 16, __half, wmma::row_major> b;
            wmma::load_matrix_sync(a, sAh + tr * 16 * HPITCH + kk * 16, HPITCH);
            wmma::load_matrix_sync(b, sBh + kk * 16 * HPITCH + tc * 16, HPITCH);
            wmma::mma_sync(c, a, b, c);
        }
        wmma::store_matrix_sync(sC + tr * 16 * CPITCH + tc * 16, c, CPITCH,
                                wmma::mem_row_major);
    }
}

// ---------------------------------------------------------------------------
// k_input: state = relu(x @ in_W + in_b); msg(fp16) = relu(state @ msg_W[0] + b0)
// ---------------------------------------------------------------------------
__global__ __launch_bounds__(256) void k_input(const float* __restrict__ x,
                       const float* __restrict__ W,  const float* __restrict__ b,
                       const float* __restrict__ mW, const float* __restrict__ mb) {
    __shared__ __half sAh[TILE_ROWS * HPITCH];
    __shared__ __half sBh[64 * HPITCH];
    __shared__ float  sC[TILE_ROWS * CPITCH];

    int tid = threadIdx.x;
    int warp = tid >> 5;
    int ty = tid >> 4, tx = tid & 15;
    int r0 = ty * 4, c0 = tx * 4;
    int blkRow = blockIdx.x * TILE_ROWS;

#pragma unroll
    for (int chunk = 0; chunk < 2; chunk++) {
        load_tileA_h(sAh, x, blkRow, FEAT, chunk * 64, tid);
        load_tileW_h(sBh, W + chunk * 64 * STATE, tid);
        __syncthreads();
        if (chunk == 0) wmma_64x64<0>(sC, sAh, sBh, warp);
        else            wmma_64x64<1>(sC, sAh, sBh, warp);
        __syncthreads();
    }

    float4 bias = *reinterpret_cast<const float4*>(&b[c0]);
    float st[4][4];
#pragma unroll
    for (int i = 0; i < 4; i++) {
        float4 v = *reinterpret_cast<const float4*>(&sC[(r0 + i) * CPITCH + c0]);
        st[i][0] = fmaxf(v.x + bias.x, 0.0f);
        st[i][1] = fmaxf(v.y + bias.y, 0.0f);
        st[i][2] = fmaxf(v.z + bias.z, 0.0f);
        st[i][3] = fmaxf(v.w + bias.w, 0.0f);
        int gr = blkRow + r0 + i;
        if (gr < N_NODES)
            *reinterpret_cast<float4*>(&g_state[gr * STATE + c0]) =
                make_float4(st[i][0], st[i][1], st[i][2], st[i][3]);
    }
    __syncthreads();

#pragma unroll
    for (int i = 0; i < 4; i++)
        st_half4(&sAh[(r0 + i) * HPITCH + c0], st[i][0], st[i][1], st[i][2], st[i][3]);
    load_tileW_h(sBh, mW, tid);
    __syncthreads();

    wmma_64x64<0>(sC, sAh, sBh, warp);
    __syncthreads();

    float4 mbias = *reinterpret_cast<const float4*>(&mb[c0]);
#pragma unroll
    for (int i = 0; i < 4; i++) {
        int gr = blkRow + r0 + i;
        if (gr < N_NODES) {
            float4 v = *reinterpret_cast<const float4*>(&sC[(r0 + i) * CPITCH + c0]);
            st_half4(&g_msg[gr * STATE + c0],
                     fmaxf(v.x + mbias.x, 0.0f),
                     fmaxf(v.y + mbias.y, 0.0f),
                     fmaxf(v.z + mbias.z, 0.0f),
                     fmaxf(v.w + mbias.w, 0.0f));
        }
    }
}

// ---------------------------------------------------------------------------
// CSR gather: agg[n] = sum_{e in csr(n)} msg[esrc[e]]   (atomic-free)
// 16 threads/node, 4-half (8B) lanes, 4-edge unroll — max threads-in-flight
// (latency-bound: R13 fp16 null result + R15 8-thread regression both confirm)
// ---------------------------------------------------------------------------
__global__ __launch_bounds__(256) void k_gather() {
    int t = blockIdx.x * blockDim.x + threadIdx.x;
    int node = t >> 4;
    if (node >= N_NODES) return;
    int c = (t & 15) << 2;                     // half-offset (x4)

    int e   = __ldg(&g_rowptr[node]);
    int end = __ldg(&g_rowptr[node + 1]);

    float4 acc = make_float4(0.f, 0.f, 0.f, 0.f);
    for (; e + 3 < end; e += 4) {
        int s0 = __ldg(&g_esrc[e]);
        int s1 = __ldg(&g_esrc[e + 1]);
        int s2 = __ldg(&g_esrc[e + 2]);
        int s3 = __ldg(&g_esrc[e + 3]);
        float4 v0 = ld_msg4(&g_msg[s0 * STATE + c]);
        float4 v1 = ld_msg4(&g_msg[s1 * STATE + c]);
        float4 v2 = ld_msg4(&g_msg[s2 * STATE + c]);
        float4 v3 = ld_msg4(&g_msg[s3 * STATE + c]);
        acc.x += (v0.x + v1.x) + (v2.x + v3.x);
        acc.y += (v0.y + v1.y) + (v2.y + v3.y);
        acc.z += (v0.z + v1.z) + (v2.z + v3.z);
        acc.w += (v0.w + v1.w) + (v2.w + v3.w);
    }
    for (; e < end; e++) {
        int s0 = __ldg(&g_esrc[e]);
        float4 v0 = ld_msg4(&g_msg[s0 * STATE + c]);
        acc.x += v0.x; acc.y += v0.y; acc.z += v0.z; acc.w += v0.w;
    }
    *reinterpret_cast<float4*>(&g_agg[node * STATE + c]) = acc;
}

// ---------------------------------------------------------------------------
// k_upd<0>: state += relu(agg @ W + b); msg(fp16) = relu(state @ mW + mb)
// k_upd<1>: LAST round — st = state + relu(agg @ W + b) pooled straight into
//           g_graph via red.v4 (no state write, no msg, no separate pool pass)
// ---------------------------------------------------------------------------
template <int LAST>
__global__ __launch_bounds__(256) void k_upd(const float* __restrict__ W,  const float* __restrict__ b,
                     const float* __restrict__ mW, const float* __restrict__ mb,
                     const int* __restrict__ batch) {
    __shared__ __half sAh[TILE_ROWS * HPITCH];
    __shared__ __half sBh[64 * HPITCH];
    __shared__ float  sC[TILE_ROWS * CPITCH];

    int tid = threadIdx.x;
    int warp = tid >> 5;
    int ty = tid >> 4, tx = tid & 15;
    int r0 = ty * 4, c0 = tx * 4;
    int blkRow = blockIdx.x * TILE_ROWS;

    load_tileA_h(sAh, g_agg, blkRow, STATE, 0, tid);
    load_tileW_h(sBh, W, tid);
    __syncthreads();

    wmma_64x64<0>(sC, sAh, sBh, warp);
    __syncthreads();

    float4 bias = *reinterpret_cast<const float4*>(&b[c0]);

    if (LAST) {
#pragma unroll
        for (int i = 0; i < 4; i++) {
            int gr = blkRow + r0 + i;
            if (gr < N_NODES) {
                float4 v   = *reinterpret_cast<const float4*>(&sC[(r0 + i) * CPITCH + c0]);
                float4 old = *reinterpret_cast<const float4*>(&g_state[gr * STATE + c0]);
                float sx = old.x + fmaxf(v.x + bias.x, 0.0f);
                float sy = old.y + fmaxf(v.y + bias.y, 0.0f);
                float sz = old.z + fmaxf(v.z + bias.z, 0.0f);
                float sw = old.w + fmaxf(v.w + bias.w, 0.0f);
                int g = __ldg(&batch[gr]);
                float* a = &g_graph[g * STATE + c0];
                asm volatile("red.global.add.v4.f32 [%0], {%1,%2,%3,%4};"
                             :: "l"(a), "f"(sx), "f"(sy), "f"(sz), "f"(sw)
                             : "memory");
            }
        }
        return;
    }

    float st[4][4];
#pragma unroll
    for (int i = 0; i < 4; i++) {
        int gr = blkRow + r0 + i;
        if (gr < N_NODES) {
            float4 v   = *reinterpret_cast<const float4*>(&sC[(r0 + i) * CPITCH + c0]);
            float4 old = *reinterpret_cast<const float4*>(&g_state[gr * STATE + c0]);
            st[i][0] = old.x + fmaxf(v.x + bias.x, 0.0f);
            st[i][1] = old.y + fmaxf(v.y + bias.y, 0.0f);
            st[i][2] = old.z + fmaxf(v.z + bias.z, 0.0f);
            st[i][3] = old.w + fmaxf(v.w + bias.w, 0.0f);
            *reinterpret_cast<float4*>(&g_state[gr * STATE + c0]) =
                make_float4(st[i][0], st[i][1], st[i][2], st[i][3]);
        } else {
            st[i][0] = st[i][1] = st[i][2] = st[i][3] = 0.0f;
        }
    }

    __syncthreads();
#pragma unroll
    for (int i = 0; i < 4; i++)
        st_half4(&sAh[(r0 + i) * HPITCH + c0], st[i][0], st[i][1], st[i][2], st[i][3]);
    load_tileW_h(sBh, mW, tid);
    __syncthreads();

    wmma_64x64<0>(sC, sAh, sBh, warp);
    __syncthreads();

    float4 mbias = *reinterpret_cast<const float4*>(&mb[c0]);
#pragma unroll
    for (int i = 0; i < 4; i++) {
        int gr = blkRow + r0 + i;
        if (gr < N_NODES) {
            float4 v = *reinterpret_cast<const float4*>(&sC[(r0 + i) * CPITCH + c0]);
            st_half4(&g_msg[gr * STATE + c0],
                     fmaxf(v.x + mbias.x, 0.0f),
                     fmaxf(v.y + mbias.y, 0.0f),
                     fmaxf(v.z + mbias.z, 0.0f),
                     fmaxf(v.w + mbias.w, 0.0f));
        }
    }
}

// ---------------------------------------------------------------------------
// mean = gs @ mean_W + mean_b ; std = exp(0.5*clip(gs @ lv_W + lv_b, -20, 2))
// ---------------------------------------------------------------------------
__global__ void k_head(const float* __restrict__ meanW, const float* __restrict__ meanB,
                       const float* __restrict__ lvW,   const float* __restrict__ lvB,
                       float* __restrict__ out) {
    __shared__ float s[STATE];
    int g = blockIdx.x;
    int m = threadIdx.x;
    s[m]      = g_graph[g * STATE + m];
    s[m + 32] = g_graph[g * STATE + m + 32];
    __syncthreads();

    float accM = meanB[m];
    float accL = lvB[m];
#pragma unroll
    for (int k = 0; k < STATE; k++) {
        float sv = s[k];
        accM = fmaf(sv, meanW[k * M_OUT + m], accM);
        accL = fmaf(sv, lvW[k * M_OUT + m], accL);
    }
    out[g * M_OUT + m] = accM;
    float lv = fminf(fmaxf(accL, -20.0f), 2.0f);
    out[N_GRAPHS * M_OUT + g * M_OUT + m] = expf(0.5f * lv);
}

// ---------------------------------------------------------------------------
extern "C" void kernel_launch(void* const* d_in, const int* in_sizes, int n_in,
                              void* d_out, int out_size) {
    const float* x     = (const float*)d_in[0];
    const int*   ei    = (const int*)d_in[1];
    const int*   batch = (const int*)d_in[2];
    const float* in_W  = (const float*)d_in[3];
    const float* in_b  = (const float*)d_in[4];
    const float* msg_W = (const float*)d_in[5];    // [4,64,64]
    const float* msg_b = (const float*)d_in[6];    // [4,64]
    const float* upd_W = (const float*)d_in[7];
    const float* upd_b = (const float*)d_in[8];
    const float* meanW = (const float*)d_in[9];
    const float* meanB = (const float*)d_in[10];
    const float* lvW   = (const float*)d_in[11];
    const float* lvB   = (const float*)d_in[12];
    float* out = (float*)d_out;

    const int edgeBlocks   = (N_EDGES + 255) / 256;
    const int gatherBlocks = (N_NODES * 16 + 255) / 256;   // 3125

    bool forked = (g_ss.s != nullptr);
    cudaStream_t cs = forked ? g_ss.s : (cudaStream_t)0;

    // Fork: CSR build runs on the side stream, overlapped with k_input.
    if (forked) {
        cudaEventRecord(g_ss.fork, 0);
        cudaStreamWaitEvent(g_ss.s, g_ss.fork, 0);
    }
    k_hist<<<edgeBlocks, 256, 0, cs>>>(ei);       // g_cnt is pre-zeroed (self-clean)
    k_scan<<<1, 1024, 0, cs>>>();                 // also zeroes g_graph + g_cnt
    k_scatter<<<edgeBlocks, 256, 0, cs>>>(ei);
    if (forked) cudaEventRecord(g_ss.join, g_ss.s);

    k_input<<<ROW_BLOCKS, 256>>>(x, in_W, in_b, msg_W, msg_b);  // state + msg[0]

    if (forked) cudaStreamWaitEvent(0, g_ss.join, 0);  // rowptr/esrc/graph ready

    for (int r = 0; r < ROUNDS; r++) {
        k_gather<<<gatherBlocks, 256>>>();
        const float* uW = upd_W + r * STATE * STATE;
        const float* ub = upd_b + r * STATE;
        if (r < ROUNDS - 1) {
            k_upd<0><<<ROW_BLOCKS, 256>>>(uW, ub,
                                          msg_W + (r + 1) * STATE * STATE,
                                          msg_b + (r + 1) * STATE, nullptr);
        } else {
            // Last round: pool fused, no state write
            k_upd<1><<<ROW_BLOCKS, 256>>>(uW, ub, nullptr, nullptr, batch);
        }
    }

    k_head<<<N_GRAPHS, M_OUT>>>(meanW, meanB, lvW, lvB, out);
}

// round 17
// speedup vs baseline: 1.1878x; 1.1878x over previous
#include <cuda_runtime.h>
#include <cuda_fp16.h>
#include <mma.h>
#include <math.h>

using namespace nvcuda;

#define N_NODES  50000
#define N_EDGES  800000
#define N_GRAPHS 256
#define FEAT     128
#define STATE    64
#define ROUNDS   4
#define M_OUT    32

#define TILE_ROWS 64
#define HPITCH    72          // half pitch (multiple of 8, conflict-skewed)
#define CPITCH    68          // float pitch for fp32 result tile
#define ROW_BLOCKS ((N_NODES + TILE_ROWS - 1) / TILE_ROWS)   // 782

// Scratch (allocation-free rule: __device__ globals)
__device__ float  g_state[N_NODES * STATE];   // 12.8 MB
__device__ __half g_msg[N_NODES * STATE];     // 6.4 MB (fp16 message buffer)
__device__ float  g_agg[N_NODES * STATE];     // 12.8 MB
__device__ float  g_graph[N_GRAPHS * STATE];  // 64 KB
// CSR-by-dst scratch (built once per launch, reused all 4 rounds)
__device__ int    g_cnt[N_NODES];
__device__ int    g_rowptr[N_NODES + 1];
__device__ int    g_cursor[N_NODES];
__device__ int    g_esrc[N_EDGES];

// ---------------------------------------------------------------------------
__global__ void k_zero() {
    int t = blockIdx.x * blockDim.x + threadIdx.x;
    if (t < N_NODES) g_cnt[t] = 0;
    if (t < N_GRAPHS * STATE) g_graph[t] = 0.0f;
}

// ---------------------------------------------------------------------------
// CSR build: histogram of dst, scan, scatter of src ids
// ---------------------------------------------------------------------------
__global__ void k_hist(const int* __restrict__ ei) {
    int t = blockIdx.x * blockDim.x + threadIdx.x;
    if (t < N_EDGES) atomicAdd(&g_cnt[__ldg(&ei[N_EDGES + t])], 1);
}

__global__ __launch_bounds__(1024) void k_scan() {
    __shared__ int ps[1024];
    const int CH = (N_NODES + 1023) / 1024;   // 49
    int t = threadIdx.x;
    int base = t * CH;

    int sum = 0;
    for (int i = 0; i < CH; i++) {
        int idx = base + i;
        if (idx < N_NODES) sum += g_cnt[idx];
    }
    ps[t] = sum;
    __syncthreads();
    for (int off = 1; off < 1024; off <<= 1) {
        int v = (t >= off) ? ps[t - off] : 0;
        __syncthreads();
        ps[t] += v;
        __syncthreads();
    }
    int run = (t == 0) ? 0 : ps[t - 1];
    for (int i = 0; i < CH; i++) {
        int idx = base + i;
        if (idx < N_NODES) {
            int c = g_cnt[idx];
            g_rowptr[idx] = run;
            g_cursor[idx] = run;
            run += c;
        }
    }
    if (t == 1023) g_rowptr[N_NODES] = run;   // = N_EDGES
}

__global__ void k_scatter(const int* __restrict__ ei) {
    int t = blockIdx.x * blockDim.x + threadIdx.x;
    if (t >= N_EDGES) return;
    int d = __ldg(&ei[N_EDGES + t]);
    int pos = atomicAdd(&g_cursor[d], 1);
    g_esrc[pos] = __ldg(&ei[t]);
}

// ===========================================================================
// fp16 helpers
// ===========================================================================
__device__ __forceinline__ float4 ld_msg4(const __half* p) {   // 4 halves (8B)
    uint2 u = *reinterpret_cast<const uint2*>(p);
    float2 f0 = __half22float2(*reinterpret_cast<__half2*>(&u.x));
    float2 f1 = __half22float2(*reinterpret_cast<__half2*>(&u.y));
    return make_float4(f0.x, f0.y, f1.x, f1.y);
}

__device__ __forceinline__ void st_half4(__half* p, float a, float b, float c, float d) {
    uint2 u;
    *reinterpret_cast<__half2*>(&u.x) = __floats2half2_rn(a, b);
    *reinterpret_cast<__half2*>(&u.y) = __floats2half2_rn(c, d);
    *reinterpret_cast<uint2*>(p) = u;
}

// ===========================================================================
// wmma GEMM building blocks (64x64 tile, fp16 in, fp32 acc)
// ===========================================================================
__device__ __forceinline__ void load_tileA_h(__half* sAh, const float* __restrict__ src,
                                             int blkRow, int rowStride, int colOff, int tid) {
#pragma unroll
    for (int p = 0; p < 4; p++) {
        int idx = p * 1024 + tid * 4;
        int row = idx >> 6, col = idx & 63;
        float4 v = make_float4(0.f, 0.f, 0.f, 0.f);
        int gr = blkRow + row;
        if (gr < N_NODES)
            v = *reinterpret_cast<const float4*>(&src[gr * rowStride + colOff + col]);
        st_half4(&sAh[row * HPITCH + col], v.x, v.y, v.z, v.w);
    }
}

__device__ __forceinline__ void load_tileW_h(__half* sBh, const float* __restrict__ W, int tid) {
#pragma unroll
    for (int p = 0; p < 4; p++) {
        int idx = p * 1024 + tid * 4;
        int row = idx >> 6, col = idx & 63;
        float4 v = *reinterpret_cast<const float4*>(&W[idx]);
        st_half4(&sBh[row * HPITCH + col], v.x, v.y, v.z, v.w);
    }
}

template <int ACCUM>
__device__ __forceinline__ void wmma_64x64(float* sC, const __half* sAh, const __half* sBh,
                                           int warp) {
#pragma unroll
    for (int t = 0; t < 2; t++) {
        int tile = warp * 2 + t;
        int tr = tile >> 2, tc = tile & 3;
        wmma::fragment<wmma::accumulator, 16, 16, 16, float> c;
        if (ACCUM)
            wmma::load_matrix_sync(c, sC + tr * 16 * CPITCH + tc * 16, CPITCH,
                                   wmma::mem_row_major);
        else
            wmma::fill_fragment(c, 0.0f);
#pragma unroll
        for (int kk = 0; kk < 4; kk++) {
            wmma::fragment<wmma::matrix_a, 16, 16, 16, __half, wmma::row_major> a;
            wmma::fragment<wmma::matrix_b, 16, 16, 16, __half, wmma::row_major> b;
            wmma::load_matrix_sync(a, sAh + tr * 16 * HPITCH + kk * 16, HPITCH);
            wmma::load_matrix_sync(b, sBh + kk * 16 * HPITCH + tc * 16, HPITCH);
            wmma::mma_sync(c, a, b, c);
        }
        wmma::store_matrix_sync(sC + tr * 16 * CPITCH + tc * 16, c, CPITCH,
                                wmma::mem_row_major);
    }
}

// ---------------------------------------------------------------------------
// k_input: state = relu(x @ in_W + in_b); msg(fp16) = relu(state @ msg_W[0] + b0)
// ---------------------------------------------------------------------------
__global__ __launch_bounds__(256) void k_input(const float* __restrict__ x,
                       const float* __restrict__ W,  const float* __restrict__ b,
                       const float* __restrict__ mW, const float* __restrict__ mb) {
    __shared__ __half sAh[TILE_ROWS * HPITCH];
    __shared__ __half sBh[64 * HPITCH];
    __shared__ float  sC[TILE_ROWS * CPITCH];

    int tid = threadIdx.x;
    int warp = tid >> 5;
    int ty = tid >> 4, tx = tid & 15;
    int r0 = ty * 4, c0 = tx * 4;
    int blkRow = blockIdx.x * TILE_ROWS;

#pragma unroll
    for (int chunk = 0; chunk < 2; chunk++) {
        load_tileA_h(sAh, x, blkRow, FEAT, chunk * 64, tid);
        load_tileW_h(sBh, W + chunk * 64 * STATE, tid);
        __syncthreads();
        if (chunk == 0) wmma_64x64<0>(sC, sAh, sBh, warp);
        else            wmma_64x64<1>(sC, sAh, sBh, warp);
        __syncthreads();
    }

    float4 bias = *reinterpret_cast<const float4*>(&b[c0]);
    float st[4][4];
#pragma unroll
    for (int i = 0; i < 4; i++) {
        float4 v = *reinterpret_cast<const float4*>(&sC[(r0 + i) * CPITCH + c0]);
        st[i][0] = fmaxf(v.x + bias.x, 0.0f);
        st[i][1] = fmaxf(v.y + bias.y, 0.0f);
        st[i][2] = fmaxf(v.z + bias.z, 0.0f);
        st[i][3] = fmaxf(v.w + bias.w, 0.0f);
        int gr = blkRow + r0 + i;
        if (gr < N_NODES)
            *reinterpret_cast<float4*>(&g_state[gr * STATE + c0]) =
                make_float4(st[i][0], st[i][1], st[i][2], st[i][3]);
    }
    __syncthreads();

#pragma unroll
    for (int i = 0; i < 4; i++)
        st_half4(&sAh[(r0 + i) * HPITCH + c0], st[i][0], st[i][1], st[i][2], st[i][3]);
    load_tileW_h(sBh, mW, tid);
    __syncthreads();

    wmma_64x64<0>(sC, sAh, sBh, warp);
    __syncthreads();

    float4 mbias = *reinterpret_cast<const float4*>(&mb[c0]);
#pragma unroll
    for (int i = 0; i < 4; i++) {
        int gr = blkRow + r0 + i;
        if (gr < N_NODES) {
            float4 v = *reinterpret_cast<const float4*>(&sC[(r0 + i) * CPITCH + c0]);
            st_half4(&g_msg[gr * STATE + c0],
                     fmaxf(v.x + mbias.x, 0.0f),
                     fmaxf(v.y + mbias.y, 0.0f),
                     fmaxf(v.z + mbias.z, 0.0f),
                     fmaxf(v.w + mbias.w, 0.0f));
        }
    }
}

// ---------------------------------------------------------------------------
// CSR gather: agg[n] = sum_{e in csr(n)} msg[esrc[e]]   (atomic-free)
// 16 threads/node, 4-half (8B) lanes, 4-edge unroll (R14 proven config)
// ---------------------------------------------------------------------------
__global__ __launch_bounds__(256) void k_gather() {
    int t = blockIdx.x * blockDim.x + threadIdx.x;
    int node = t >> 4;
    if (node >= N_NODES) return;
    int c = (t & 15) << 2;                     // half-offset (x4)

    int e   = __ldg(&g_rowptr[node]);
    int end = __ldg(&g_rowptr[node + 1]);

    float4 acc = make_float4(0.f, 0.f, 0.f, 0.f);
    for (; e + 3 < end; e += 4) {
        int s0 = __ldg(&g_esrc[e]);
        int s1 = __ldg(&g_esrc[e + 1]);
        int s2 = __ldg(&g_esrc[e + 2]);
        int s3 = __ldg(&g_esrc[e + 3]);
        float4 v0 = ld_msg4(&g_msg[s0 * STATE + c]);
        float4 v1 = ld_msg4(&g_msg[s1 * STATE + c]);
        float4 v2 = ld_msg4(&g_msg[s2 * STATE + c]);
        float4 v3 = ld_msg4(&g_msg[s3 * STATE + c]);
        acc.x += (v0.x + v1.x) + (v2.x + v3.x);
        acc.y += (v0.y + v1.y) + (v2.y + v3.y);
        acc.z += (v0.z + v1.z) + (v2.z + v3.z);
        acc.w += (v0.w + v1.w) + (v2.w + v3.w);
    }
    for (; e < end; e++) {
        int s0 = __ldg(&g_esrc[e]);
        float4 v0 = ld_msg4(&g_msg[s0 * STATE + c]);
        acc.x += v0.x; acc.y += v0.y; acc.z += v0.z; acc.w += v0.w;
    }
    *reinterpret_cast<float4*>(&g_agg[node * STATE + c]) = acc;
}

// ---------------------------------------------------------------------------
// k_upd<0>: state += relu(agg @ W + b); msg(fp16) = relu(state @ mW + mb)
// k_upd<1>: LAST round — st = state + relu(agg @ W + b) pooled straight into
//           g_graph via red.v4 (no state write, no msg, no separate pool pass)
// ---------------------------------------------------------------------------
template <int LAST>
__global__ __launch_bounds__(256) void k_upd(const float* __restrict__ W,  const float* __restrict__ b,
                     const float* __restrict__ mW, const float* __restrict__ mb,
                     const int* __restrict__ batch) {
    __shared__ __half sAh[TILE_ROWS * HPITCH];
    __shared__ __half sBh[64 * HPITCH];
    __shared__ float  sC[TILE_ROWS * CPITCH];

    int tid = threadIdx.x;
    int warp = tid >> 5;
    int ty = tid >> 4, tx = tid & 15;
    int r0 = ty * 4, c0 = tx * 4;
    int blkRow = blockIdx.x * TILE_ROWS;

    load_tileA_h(sAh, g_agg, blkRow, STATE, 0, tid);
    load_tileW_h(sBh, W, tid);
    __syncthreads();

    wmma_64x64<0>(sC, sAh, sBh, warp);
    __syncthreads();

    float4 bias = *reinterpret_cast<const float4*>(&b[c0]);

    if (LAST) {
#pragma unroll
        for (int i = 0; i < 4; i++) {
            int gr = blkRow + r0 + i;
            if (gr < N_NODES) {
                float4 v   = *reinterpret_cast<const float4*>(&sC[(r0 + i) * CPITCH + c0]);
                float4 old = *reinterpret_cast<const float4*>(&g_state[gr * STATE + c0]);
                float sx = old.x + fmaxf(v.x + bias.x, 0.0f);
                float sy = old.y + fmaxf(v.y + bias.y, 0.0f);
                float sz = old.z + fmaxf(v.z + bias.z, 0.0f);
                float sw = old.w + fmaxf(v.w + bias.w, 0.0f);
                int g = __ldg(&batch[gr]);
                float* a = &g_graph[g * STATE + c0];
                asm volatile("red.global.add.v4.f32 [%0], {%1,%2,%3,%4};"
                             :: "l"(a), "f"(sx), "f"(sy), "f"(sz), "f"(sw)
                             : "memory");
            }
        }
        return;
    }

    float st[4][4];
#pragma unroll
    for (int i = 0; i < 4; i++) {
        int gr = blkRow + r0 + i;
        if (gr < N_NODES) {
            float4 v   = *reinterpret_cast<const float4*>(&sC[(r0 + i) * CPITCH + c0]);
            float4 old = *reinterpret_cast<const float4*>(&g_state[gr * STATE + c0]);
            st[i][0] = old.x + fmaxf(v.x + bias.x, 0.0f);
            st[i][1] = old.y + fmaxf(v.y + bias.y, 0.0f);
            st[i][2] = old.z + fmaxf(v.z + bias.z, 0.0f);
            st[i][3] = old.w + fmaxf(v.w + bias.w, 0.0f);
            *reinterpret_cast<float4*>(&g_state[gr * STATE + c0]) =
                make_float4(st[i][0], st[i][1], st[i][2], st[i][3]);
        } else {
            st[i][0] = st[i][1] = st[i][2] = st[i][3] = 0.0f;
        }
    }

    __syncthreads();
#pragma unroll
    for (int i = 0; i < 4; i++)
        st_half4(&sAh[(r0 + i) * HPITCH + c0], st[i][0], st[i][1], st[i][2], st[i][3]);
    load_tileW_h(sBh, mW, tid);
    __syncthreads();

    wmma_64x64<0>(sC, sAh, sBh, warp);
    __syncthreads();

    float4 mbias = *reinterpret_cast<const float4*>(&mb[c0]);
#pragma unroll
    for (int i = 0; i < 4; i++) {
        int gr = blkRow + r0 + i;
        if (gr < N_NODES) {
            float4 v = *reinterpret_cast<const float4*>(&sC[(r0 + i) * CPITCH + c0]);
            st_half4(&g_msg[gr * STATE + c0],
                     fmaxf(v.x + mbias.x, 0.0f),
                     fmaxf(v.y + mbias.y, 0.0f),
                     fmaxf(v.z + mbias.z, 0.0f),
                     fmaxf(v.w + mbias.w, 0.0f));
        }
    }
}

// ---------------------------------------------------------------------------
// mean = gs @ mean_W + mean_b ; std = exp(0.5*clip(gs @ lv_W + lv_b, -20, 2))
// ---------------------------------------------------------------------------
__global__ void k_head(const float* __restrict__ meanW, const float* __restrict__ meanB,
                       const float* __restrict__ lvW,   const float* __restrict__ lvB,
                       float* __restrict__ out) {
    __shared__ float s[STATE];
    int g = blockIdx.x;
    int m = threadIdx.x;
    s[m]      = g_graph[g * STATE + m];
    s[m + 32] = g_graph[g * STATE + m + 32];
    __syncthreads();

    float accM = meanB[m];
    float accL = lvB[m];
#pragma unroll
    for (int k = 0; k < STATE; k++) {
        float sv = s[k];
        accM = fmaf(sv, meanW[k * M_OUT + m], accM);
        accL = fmaf(sv, lvW[k * M_OUT + m], accL);
    }
    out[g * M_OUT + m] = accM;
    float lv = fminf(fmaxf(accL, -20.0f), 2.0f);
    out[N_GRAPHS * M_OUT + g * M_OUT + m] = expf(0.5f * lv);
}

// ---------------------------------------------------------------------------
extern "C" void kernel_launch(void* const* d_in, const int* in_sizes, int n_in,
                              void* d_out, int out_size) {
    const float* x     = (const float*)d_in[0];
    const int*   ei    = (const int*)d_in[1];
    const int*   batch = (const int*)d_in[2];
    const float* in_W  = (const float*)d_in[3];
    const float* in_b  = (const float*)d_in[4];
    const float* msg_W = (const float*)d_in[5];    // [4,64,64]
    const float* msg_b = (const float*)d_in[6];    // [4,64]
    const float* upd_W = (const float*)d_in[7];
    const float* upd_b = (const float*)d_in[8];
    const float* meanW = (const float*)d_in[9];
    const float* meanB = (const float*)d_in[10];
    const float* lvW   = (const float*)d_in[11];
    const float* lvB   = (const float*)d_in[12];
    float* out = (float*)d_out;

    const int zeroBlocks   = (N_NODES + 255) / 256;
    const int edgeBlocks   = (N_EDGES + 255) / 256;
    const int gatherBlocks = (N_NODES * 16 + 255) / 256;   // 3125

    // CSR build (once per launch; reused by all 4 rounds) — default stream,
    // same as the 227.9us R14 baseline (no fork: condemned pending evidence)
    k_zero<<<zeroBlocks, 256>>>();
    k_hist<<<edgeBlocks, 256>>>(ei);
    k_scan<<<1, 1024>>>();
    k_scatter<<<edgeBlocks, 256>>>(ei);

    k_input<<<ROW_BLOCKS, 256>>>(x, in_W, in_b, msg_W, msg_b);  // state + msg[0]

    for (int r = 0; r < ROUNDS; r++) {
        k_gather<<<gatherBlocks, 256>>>();
        const float* uW = upd_W + r * STATE * STATE;
        const float* ub = upd_b + r * STATE;
        if (r < ROUNDS - 1) {
            k_upd<0><<<ROW_BLOCKS, 256>>>(uW, ub,
                                          msg_W + (r + 1) * STATE * STATE,
                                          msg_b + (r + 1) * STATE, nullptr);
        } else {
            // ONLY change vs R14: last round pools directly, no state write,
            // and k_pool is deleted
            k_upd<1><<<ROW_BLOCKS, 256>>>(uW, ub, nullptr, nullptr, batch);
        }
    }

    k_head<<<N_GRAPHS, M_OUT>>>(meanW, meanB, lvW, lvB, out);
}